// round 13
// baseline (speedup 1.0000x reference)
#include <cuda_runtime.h>
#include <cstdint>

// CoordsToNRF: out[b, p] = atoms_flat[p] * (AU2KCALMOLA / MAX_NRF) / ||c_i - c_j||^2
// p = i*(i-1)/2 + j over the strict lower triangle of 128 atoms. B=2048, NC2=8128.
//
// Round-13: R11's 2-batch f32x2 body with fully static row scheduling.
// Warp w sweeps tile t (j0=32t) rows i = j0 + w + 8k, k < 16-4t (constant
// trips, fully unrolled). partial <=> k<4 is compile-time, so 60% of rows
// have zero predicate/clamp overhead. 8 warps x batch pair, grid 1024.

#define N_ATOMS 128
#define NC2     8128
#define BLOCK_THREADS 256      // 8 warps, one batch PAIR per block

typedef unsigned long long u64;

__device__ __forceinline__ u64 f2_add(u64 a, u64 b) {
    u64 r; asm("add.rn.f32x2 %0, %1, %2;" : "=l"(r) : "l"(a), "l"(b)); return r;
}
__device__ __forceinline__ u64 f2_mul(u64 a, u64 b) {
    u64 r; asm("mul.rn.f32x2 %0, %1, %2;" : "=l"(r) : "l"(a), "l"(b)); return r;
}
__device__ __forceinline__ u64 f2_fma(u64 a, u64 b, u64 c) {
    u64 r; asm("fma.rn.f32x2 %0, %1, %2, %3;" : "=l"(r) : "l"(a), "l"(b), "l"(c)); return r;
}
__device__ __forceinline__ float2 f2_lohi(u64 v) {
    float2 f; asm("mov.b64 {%0, %1}, %2;" : "=f"(f.x), "=f"(f.y) : "l"(v)); return f;
}

__device__ __forceinline__ float nrf_scale() {
    return (float)(627.5095 * 0.529177 / 100.0);
}

// One j-tile: J0 = 32*t, KCNT = 16 - 4*t rows per warp at stride 8.
template <int J0, int KCNT>
__device__ __forceinline__ void do_tile(const float* __restrict__ sc,
                                        const float* __restrict__ atoms,
                                        float* __restrict__ ob,
                                        int warp, int lane, float scale) {
    const u64 S = 0x8000000080000000ull;       // packed f32x2 sign flip
    const int j = J0 + lane;

    // cj pair from smem as 64-bit lane pairs, negated once per tile.
    const ulonglong2 cj_xy = *reinterpret_cast<const ulonglong2*>(&sc[j * 8]);
    const u64        cj_z  = *reinterpret_cast<const u64*>(&sc[j * 8 + 4]);
    const u64 ncjx = cj_xy.x ^ S;
    const u64 ncjy = cj_xy.y ^ S;
    const u64 ncjz = cj_z   ^ S;

    const int i0 = J0 + warp;                  // k = 0 row
    const float* ci_base = &sc[i0 * 8];        // +64 floats (256B) per k

    #pragma unroll
    for (int k = 0; k < KCNT; k++) {
        const int i = i0 + 8 * k;
        // ci pair: LDS.128 + LDS.64 at [reg + imm], uniform addr -> broadcast.
        const ulonglong2 cixy = *reinterpret_cast<const ulonglong2*>(ci_base + 64 * k);
        const u64        ciz  = *reinterpret_cast<const u64*>(ci_base + 64 * k + 4);

        const u64 dx2 = f2_add(cixy.x, ncjx);
        const u64 dy2 = f2_add(cixy.y, ncjy);
        const u64 dz2 = f2_add(ciz,    ncjz);
        const u64 d2p = f2_fma(dz2, dz2, f2_fma(dy2, dy2, f2_mul(dx2, dx2)));
        const float2 d2 = f2_lohi(d2p);

        const int p = ((i * (i - 1)) >> 1) + j;

        if (k < 4) {
            // Partial rows (i < J0+32): clamp LDG (tile3 edge), predicate stores.
            const int pc = (p < NC2 - 1) ? p : (NC2 - 1);
            const float aval = __ldg(&atoms[pc]) * scale;
            const float ra = __fdividef(aval, d2.x);
            const float rb = __fdividef(aval, d2.y);
            if (j < i) {
                ob[p]       = ra;
                ob[p + NC2] = rb;
            }
        } else {
            // Full rows: all 32 lanes valid, unconditional.
            const float aval = __ldg(&atoms[p]) * scale;
            ob[p]       = __fdividef(aval, d2.x);
            ob[p + NC2] = __fdividef(aval, d2.y);
        }
    }
}

__global__ __launch_bounds__(BLOCK_THREADS, 7)
void coords_to_nrf_kernel(const float* __restrict__ coords,
                          const float* __restrict__ atoms_flat,
                          float* __restrict__ out) {
    // Packed pair coords: atom a -> {x0,x1,y0,y1,z0,z1,pad,pad}: 4KB.
    __shared__ __align__(16) float sc[N_ATOMS * 8];

    const int warp = threadIdx.x >> 5;
    const int lane = threadIdx.x & 31;
    const int bg   = blockIdx.x;           // batch pair index

    // ---- Stage batch pair (gmem [b][atom][3] -> packed-pair smem) ----
    const float* cb = coords + (size_t)bg * 2 * (N_ATOMS * 3);
    #pragma unroll
    for (int idx = threadIdx.x; idx < 2 * N_ATOMS * 3; idx += BLOCK_THREADS) {
        const int q   = idx / (N_ATOMS * 3);
        const int rem = idx - q * (N_ATOMS * 3);
        const int a   = rem / 3;
        const int d   = rem - a * 3;
        sc[a * 8 + d * 2 + q] = cb[idx];
    }
    __syncthreads();

    const float scale = nrf_scale();
    float* ob = out + (size_t)bg * 2 * NC2;

    do_tile<0,  16>(sc, atoms_flat, ob, warp, lane, scale);   // j in [0,32)
    do_tile<32, 12>(sc, atoms_flat, ob, warp, lane, scale);   // j in [32,64)
    do_tile<64,  8>(sc, atoms_flat, ob, warp, lane, scale);   // j in [64,96)
    do_tile<96,  4>(sc, atoms_flat, ob, warp, lane, scale);   // j in [96,128)
}

extern "C" void kernel_launch(void* const* d_in, const int* in_sizes, int n_in,
                              void* d_out, int out_size) {
    const float* coords     = (const float*)d_in[0];  // [2048, 128, 3] f32
    const float* atoms_flat = (const float*)d_in[1];  // [8128] f32
    float* out = (float*)d_out;                       // [2048, 8128] f32

    const int batch = in_sizes[0] / (N_ATOMS * 3);    // 2048
    coords_to_nrf_kernel<<<batch / 2, BLOCK_THREADS>>>(coords, atoms_flat, out);
}

// round 14
// speedup vs baseline: 5.3991x; 5.3991x over previous
#include <cuda_runtime.h>
#include <cstdint>

// CoordsToNRF: out[b, p] = atoms_flat[p] * (AU2KCALMOLA / MAX_NRF) / ||c_i - c_j||^2
// p = i*(i-1)/2 + j over the strict lower triangle of 128 atoms. B=2048, NC2=8128.
//
// Round-14: R11 (best: flat chunks, consecutive-i sweep -> dense in-order
// stores) plus: (1) coords pre-scaled by sqrt(1/scale) at staging so the
// per-row aval*scale FMUL vanishes; (2) each segment split into partial rows
// (clamp+predicate) and full rows (unconditional) at the warp-uniform
// boundary i = j0+32.

#define N_ATOMS 128
#define NC2     8128
#define BLOCK_THREADS 256      // 8 warps, one batch PAIR per block

// sqrt(1 / (627.5095 * 0.529177 / 100.0)) computed in double, rounded:
// scale = 3.32063595..., sqrt(1/scale) = 0.54876830...
#define COORD_PRESCALE 0.5487683f

typedef unsigned long long u64;

__device__ __forceinline__ u64 f2_add(u64 a, u64 b) {
    u64 r; asm("add.rn.f32x2 %0, %1, %2;" : "=l"(r) : "l"(a), "l"(b)); return r;
}
__device__ __forceinline__ u64 f2_mul(u64 a, u64 b) {
    u64 r; asm("mul.rn.f32x2 %0, %1, %2;" : "=l"(r) : "l"(a), "l"(b)); return r;
}
__device__ __forceinline__ u64 f2_fma(u64 a, u64 b, u64 c) {
    u64 r; asm("fma.rn.f32x2 %0, %1, %2, %3;" : "=l"(r) : "l"(a), "l"(b), "l"(c)); return r;
}
__device__ __forceinline__ float2 f2_lohi(u64 v) {
    float2 f; asm("mov.b64 {%0, %1}, %2;" : "=f"(f.x), "=f"(f.y) : "l"(v)); return f;
}

__global__ __launch_bounds__(BLOCK_THREADS, 7)
void coords_to_nrf_kernel(const float* __restrict__ coords,
                          const float* __restrict__ atoms_flat,
                          float* __restrict__ out) {
    // Packed pair coords (pre-scaled): atom a -> {x0,x1,y0,y1,z0,z1,pad,pad}.
    __shared__ __align__(16) float sc[N_ATOMS * 8];

    const int warp = threadIdx.x >> 5;    // 0..7 -> row chunk
    const int lane = threadIdx.x & 31;
    const int bg   = blockIdx.x;          // batch pair index

    // ---- Stage batch pair, pre-scaled by sqrt(1/scale) ----
    const float* cb = coords + (size_t)bg * 2 * (N_ATOMS * 3);
    #pragma unroll
    for (int idx = threadIdx.x; idx < 2 * N_ATOMS * 3; idx += BLOCK_THREADS) {
        const int q   = idx / (N_ATOMS * 3);       // batch in pair
        const int rem = idx - q * (N_ATOMS * 3);
        const int a   = rem / 3;
        const int d   = rem - a * 3;
        sc[a * 8 + d * 2 + q] = cb[idx] * COORD_PRESCALE;
    }
    __syncthreads();

    const u64 S = 0x8000000080000000ull;           // packed f32x2 sign flip

    // Flat rows [0,316) split: 40,40,40,40,39,39,39,39.
    const int over = (warp > 4) ? (warp - 4) : 0;
    const int r0 = 40 * warp - over;
    const int r1 = r0 + ((warp < 4) ? 40 : 39);

    const int starts[5] = {0, 127, 222, 285, 316};

    float* ob = out + (size_t)bg * 2 * NC2;        // batch q=0 plane

    #pragma unroll
    for (int seg = 0; seg < 4; seg++) {
        const int a = (r0 > starts[seg])     ? r0 : starts[seg];
        const int b = (r1 < starts[seg + 1]) ? r1 : starts[seg + 1];
        if (a >= b) continue;

        const int j0 = seg * 32;
        const int j  = j0 + lane;

        // cj pair straight from smem as 64-bit lane pairs, negated once.
        const ulonglong2 cj_xy = *reinterpret_cast<const ulonglong2*>(&sc[j * 8]);
        const u64        cj_z  = *reinterpret_cast<const u64*>(&sc[j * 8 + 4]);
        const u64 ncjx = cj_xy.x ^ S;
        const u64 ncjy = cj_xy.y ^ S;
        const u64 ncjz = cj_z   ^ S;

        const int i0   = j0 + 1 + (a - starts[seg]);
        const int iend = i0 + (b - a);
        // Rows with i < j0+32 are partial (per-lane mask); i >= j0+32 full.
        const int im_raw = j0 + 32;
        const int im = (iend < im_raw) ? iend : ((i0 > im_raw) ? i0 : im_raw);

        int pbase = (i0 * (i0 - 1)) >> 1;

        // ---- partial rows: clamp LDG, predicated stores ----
        #pragma unroll 4
        for (int i = i0; i < im; i++) {
            const ulonglong2 cixy = *reinterpret_cast<const ulonglong2*>(&sc[i * 8]);
            const u64        ciz  = *reinterpret_cast<const u64*>(&sc[i * 8 + 4]);

            const u64 dx2 = f2_add(cixy.x, ncjx);
            const u64 dy2 = f2_add(cixy.y, ncjy);
            const u64 dz2 = f2_add(ciz,    ncjz);
            const u64 d2p = f2_fma(dz2, dz2, f2_fma(dy2, dy2, f2_mul(dx2, dx2)));
            const float2 d2 = f2_lohi(d2p);

            const int p  = pbase + j;
            const int pc = (p < NC2 - 1) ? p : (NC2 - 1);  // masked-lane safety
            const float aval = __ldg(&atoms_flat[pc]);     // scale folded in d2
            const float ra = __fdividef(aval, d2.x);        // batch 0
            const float rb = __fdividef(aval, d2.y);        // batch 1

            if (j < i) {               // bare predicated store pair -> @P STG
                ob[p]       = ra;
                ob[p + NC2] = rb;
            }
            pbase += i;
        }

        // ---- full rows: all 32 lanes valid, no clamp, no predicate ----
        #pragma unroll 4
        for (int i = im; i < iend; i++) {
            const ulonglong2 cixy = *reinterpret_cast<const ulonglong2*>(&sc[i * 8]);
            const u64        ciz  = *reinterpret_cast<const u64*>(&sc[i * 8 + 4]);

            const u64 dx2 = f2_add(cixy.x, ncjx);
            const u64 dy2 = f2_add(cixy.y, ncjy);
            const u64 dz2 = f2_add(ciz,    ncjz);
            const u64 d2p = f2_fma(dz2, dz2, f2_fma(dy2, dy2, f2_mul(dx2, dx2)));
            const float2 d2 = f2_lohi(d2p);

            const int p = pbase + j;
            const float aval = __ldg(&atoms_flat[p]);

            ob[p]       = __fdividef(aval, d2.x);
            ob[p + NC2] = __fdividef(aval, d2.y);
            pbase += i;
        }
    }
}

extern "C" void kernel_launch(void* const* d_in, const int* in_sizes, int n_in,
                              void* d_out, int out_size) {
    const float* coords     = (const float*)d_in[0];  // [2048, 128, 3] f32
    const float* atoms_flat = (const float*)d_in[1];  // [8128] f32
    float* out = (float*)d_out;                       // [2048, 8128] f32

    const int batch = in_sizes[0] / (N_ATOMS * 3);    // 2048
    coords_to_nrf_kernel<<<batch / 2, BLOCK_THREADS>>>(coords, atoms_flat, out);
}